// round 16
// baseline (speedup 1.0000x reference)
#include <cuda_runtime.h>
#include <math.h>

// Moments stored TRANSPOSED: g_mom[i * BMAX + b] so gn_kernel's per-index
// load is coalesced across its 256 consecutive-batch threads.
#define BMAX 1024
__device__ float g_mom[72 * BMAX];
__device__ int   g_ticket;   // completion counter; gn resets it each replay

// ----------------------------------------------------------------------------
// Kernel A: per-batch moment reduction (measured ~4.9us), transposed write,
// release-ticket at end for the concurrently-running gn_kernel.
// ----------------------------------------------------------------------------
__global__ __launch_bounds__(256) void moments_kernel(
    const float* __restrict__ src4, const float* __restrict__ trg4,
    const float* __restrict__ wgt, const float* __restrict__ invc, int N)
{
    const int TP = 256;
    int b   = blockIdx.x;
    int tid = threadIdx.x;
    const float* sb = src4 + (size_t)b * 4 * N;
    const float* tb = trg4 + (size_t)b * 4 * N;
    const float* wb = wgt  + (size_t)b * N;
    const float* cb = invc + (size_t)b * N * 9;

    __shared__ float4 smc4[2][TP * 9 / 4];

    float acc[72];
#pragma unroll
    for (int i = 0; i < 72; i++) acc[i] = 0.f;

    int full_tiles = N / TP;

    float4 r0, r1, r2;
    if (full_tiles > 0) {
        const float4* p = (const float4*)(cb);
        r0 = p[tid];
        r1 = p[tid + 256];
        if (tid < 64) r2 = p[tid + 512];
        smc4[0][tid] = r0;
        smc4[0][tid + 256] = r1;
        if (tid < 64) smc4[0][tid + 512] = r2;
    }
    __syncthreads();

    for (int tl = 0; tl < full_tiles; tl++) {
        if (tl + 1 < full_tiles) {
            const float4* p = (const float4*)(cb + (size_t)(tl + 1) * TP * 9);
            r0 = p[tid];
            r1 = p[tid + 256];
            if (tid < 64) r2 = p[tid + 512];
        }

        int n = tl * TP + tid;
        {
            float sx = sb[n], sy = sb[N + n], sz = sb[2 * N + n];
            float tx = tb[n], ty = tb[N + n], tz = tb[2 * N + n];
            float w  = wb[n];
            float u  = 2.f * w * w;
            const float* c = (const float*)smc4[tl & 1] + tid * 9;
            float Wp[6];
            Wp[0] = u * c[0]; Wp[1] = u * c[1]; Wp[2] = u * c[2];
            Wp[3] = u * c[4]; Wp[4] = u * c[5]; Wp[5] = u * c[8];
            float sv[3] = {sx, sy, sz};
            float sp[6] = {sx * sx, sx * sy, sx * sz, sy * sy, sy * sz, sz * sz};

#pragma unroll
            for (int p = 0; p < 6; p++) acc[p] += Wp[p];
#pragma unroll
            for (int p = 0; p < 6; p++)
#pragma unroll
                for (int cc = 0; cc < 3; cc++) acc[6 + p * 3 + cc] += Wp[p] * sv[cc];
#pragma unroll
            for (int p = 0; p < 6; p++)
#pragma unroll
                for (int mc = 0; mc < 6; mc++) acc[24 + p * 6 + mc] += Wp[p] * sp[mc];

            float wt0 = Wp[0] * tx + Wp[1] * ty + Wp[2] * tz;
            float wt1 = Wp[1] * tx + Wp[3] * ty + Wp[4] * tz;
            float wt2 = Wp[2] * tx + Wp[4] * ty + Wp[5] * tz;
            acc[60] += wt0; acc[61] += wt1; acc[62] += wt2;
            float wt[3] = {wt0, wt1, wt2};
#pragma unroll
            for (int a = 0; a < 3; a++)
#pragma unroll
                for (int m2 = 0; m2 < 3; m2++) acc[63 + a * 3 + m2] += wt[a] * sv[m2];
        }

        if (tl + 1 < full_tiles) {
            __syncthreads();
            int nb = (tl + 1) & 1;
            smc4[nb][tid] = r0;
            smc4[nb][tid + 256] = r1;
            if (tid < 64) smc4[nb][tid + 512] = r2;
            __syncthreads();
        }
    }

    for (int n = full_tiles * TP + tid; n < N; n += 256) {
        float sx = sb[n], sy = sb[N + n], sz = sb[2 * N + n];
        float tx = tb[n], ty = tb[N + n], tz = tb[2 * N + n];
        float w  = wb[n];
        float u  = 2.f * w * w;
        const float* c = cb + (size_t)n * 9;
        float Wp[6];
        Wp[0] = u * c[0]; Wp[1] = u * c[1]; Wp[2] = u * c[2];
        Wp[3] = u * c[4]; Wp[4] = u * c[5]; Wp[5] = u * c[8];
        float sv[3] = {sx, sy, sz};
        float sp[6] = {sx * sx, sx * sy, sx * sz, sy * sy, sy * sz, sz * sz};
#pragma unroll
        for (int p = 0; p < 6; p++) acc[p] += Wp[p];
#pragma unroll
        for (int p = 0; p < 6; p++)
#pragma unroll
            for (int cc = 0; cc < 3; cc++) acc[6 + p * 3 + cc] += Wp[p] * sv[cc];
#pragma unroll
        for (int p = 0; p < 6; p++)
#pragma unroll
            for (int mc = 0; mc < 6; mc++) acc[24 + p * 6 + mc] += Wp[p] * sp[mc];
        float wt0 = Wp[0] * tx + Wp[1] * ty + Wp[2] * tz;
        float wt1 = Wp[1] * tx + Wp[3] * ty + Wp[4] * tz;
        float wt2 = Wp[2] * tx + Wp[4] * ty + Wp[5] * tz;
        acc[60] += wt0; acc[61] += wt1; acc[62] += wt2;
        float wt[3] = {wt0, wt1, wt2};
#pragma unroll
        for (int a = 0; a < 3; a++)
#pragma unroll
            for (int m2 = 0; m2 < 3; m2++) acc[63 + a * 3 + m2] += wt[a] * sv[m2];
    }

#pragma unroll
    for (int i = 0; i < 72; i++) {
        float v = acc[i];
#pragma unroll
        for (int off = 16; off; off >>= 1) v += __shfl_down_sync(0xffffffffu, v, off);
        acc[i] = v;
    }
    __shared__ float red[8][72];
    int wid = tid >> 5, lane = tid & 31;
    __syncthreads();
    if (lane == 0) {
#pragma unroll
        for (int i = 0; i < 72; i++) red[wid][i] = acc[i];
    }
    __syncthreads();
    if (tid < 72) {
        float v = 0.f;
#pragma unroll
        for (int wdx = 0; wdx < 8; wdx++) v += red[wdx][tid];
        g_mom[tid * BMAX + b] = v;     // transposed write
    }

    // release ticket: writes above become device-visible before the count.
    __threadfence();
    __syncthreads();
    if (tid == 0) atomicAdd(&g_ticket, 1);
}

// ----------------------------------------------------------------------------
// Packed f32x2 primitives (SASS FFMA2 — only reachable via PTX)
// ----------------------------------------------------------------------------
typedef unsigned long long ull;
#define PK(d, lo, hi)  asm("mov.b64 %0, {%1,%2};" : "=l"(d) : "f"(lo), "f"(hi))
#define UPK(lo, hi, s) asm("mov.b64 {%0,%1}, %2;" : "=f"(lo), "=f"(hi) : "l"(s))
#define FMA2(d, a, b, c) asm("fma.rn.f32x2 %0, %1, %2, %3;" : "=l"(d) : "l"(a), "l"(b), "l"(c))
#define MUL2(d, a, b)    asm("mul.rn.f32x2 %0, %1, %2;"     : "=l"(d) : "l"(a), "l"(b))

// fast reciprocal: MUFU.RCP + one Newton step (~1e-7 rel err)
static __device__ __forceinline__ float frcp(float d)
{
    float r;
    asm("rcp.approx.f32 %0, %1;" : "=f"(r) : "f"(d));
    return r * (2.f - d * r);
}

// TWO congruences R^T W R at once (bit-identical per lane to scalar FFMA).
static __device__ __forceinline__ void congr2(const ull Rp[9], const ull W[6],
                                              float oa[6], float ob[6])
{
    ull Y[9];
#pragma unroll
    for (int j = 0; j < 3; j++) {
        ull y;
        MUL2(y, W[0], Rp[j]); FMA2(y, W[1], Rp[3 + j], y); FMA2(y, W[2], Rp[6 + j], y);
        Y[j] = y;
        MUL2(y, W[1], Rp[j]); FMA2(y, W[3], Rp[3 + j], y); FMA2(y, W[4], Rp[6 + j], y);
        Y[3 + j] = y;
        MUL2(y, W[2], Rp[j]); FMA2(y, W[4], Rp[3 + j], y); FMA2(y, W[5], Rp[6 + j], y);
        Y[6 + j] = y;
    }
    int k = 0;
#pragma unroll
    for (int p = 0; p < 3; p++)
#pragma unroll
        for (int q = p; q < 3; q++) {
            ull o;
            MUL2(o, Rp[p], Y[q]); FMA2(o, Rp[3 + p], Y[3 + q], o); FMA2(o, Rp[6 + p], Y[6 + q], o);
            UPK(oa[k], ob[k], o);
            k++;
        }
}

// symmetric 3x3 inverse via cofactors (shallow chain, one rcp)
// in : s00,s01,s02,s11,s12,s22  out: i[6] same order
static __device__ __forceinline__ void inv3sym(
    float s00, float s01, float s02, float s11, float s12, float s22, float i[6])
{
    float c0 = s11 * s22 - s12 * s12;
    float c1 = s02 * s12 - s01 * s22;
    float c2 = s01 * s12 - s02 * s11;
    float det = s00 * c0 + s01 * c1 + s02 * c2;
    float id = frcp(det);
    i[0] = c0 * id;
    i[1] = c1 * id;
    i[2] = c2 * id;
    i[3] = (s00 * s22 - s02 * s02) * id;
    i[4] = (s01 * s02 - s00 * s12) * id;
    i[5] = (s00 * s11 - s01 * s01) * id;
}

static __device__ __forceinline__ void se3exp(const float xi[6], float Re[9], float te[3])
{
    float r0 = xi[0], r1 = xi[1], r2 = xi[2];
    float p0 = xi[3], p1 = xi[4], p2 = xi[5];
    float th2 = p0 * p0 + p1 * p1 + p2 * p2;
    float A, Bc, Cc;
    if (th2 < 1e-12f) {
        A = 1.f; Bc = 0.5f; Cc = 1.f / 6.f;
    } else {
        float rth  = rsqrtf(th2);
        float th   = th2 * rth;
        float sn   = __sinf(th), cs = __cosf(th);
        float ith2 = rth * rth;
        A  = sn * rth;
        Bc = (1.f - cs) * ith2;
        Cc = (th - sn) * ith2 * rth;
    }
    float K[9]  = {0.f, -p2, p1, p2, 0.f, -p0, -p1, p0, 0.f};
    float pp[9] = {p0 * p0, p0 * p1, p0 * p2,
                   p1 * p0, p1 * p1, p1 * p2,
                   p2 * p0, p2 * p1, p2 * p2};
    float V[9];
#pragma unroll
    for (int i = 0; i < 9; i++) {
        float diag = (i == 0 || i == 4 || i == 8) ? 1.f : 0.f;
        float K2   = pp[i] - ((i == 0 || i == 4 || i == 8) ? th2 : 0.f);
        Re[i] = diag + A * K[i] + Bc * K2;
        V[i]  = diag + Bc * K[i] + Cc * K2;
    }
#pragma unroll
    for (int a = 0; a < 3; a++)
        te[a] = V[a * 3 + 0] * r0 + V[a * 3 + 1] * r1 + V[a * 3 + 2] * r2;
}

// ----------------------------------------------------------------------------
// Kernel B: Gauss-Newton (packed congruences, __launch_bounds__(256,1)).
// NEW: the 6x6 SPD solve is a block-Schur analytic solve with two cofactor
// 3x3 inverses (shallow ~45-level chain, 2 reciprocals) replacing the
// Cholesky's ~150-level chain with 6 dependent rsqrts.
// Spin-waits on g_ticket (concurrent launch with moments_kernel).
// ----------------------------------------------------------------------------
__global__ __launch_bounds__(256, 1) void gn_kernel(
    const float* __restrict__ Tinit, const float* __restrict__ Tsv,
    float* __restrict__ out, int B)
{
    // --- wait for all moment blocks ---
    if (threadIdx.x == 0 && blockIdx.x == 0) {
        int v;
        do {
            asm volatile("ld.global.acquire.gpu.b32 %0, [%1];" : "=r"(v) : "l"(&g_ticket));
            if (v < B) __nanosleep(64);
        } while (v < B);
        atomicExch(&g_ticket, 0);   // reset for next replay
    }
    __syncthreads();

    int b = blockIdx.x * 256 + threadIdx.x;
    if (b >= B) return;

    float m[72];
#pragma unroll
    for (int i = 0; i < 72; i++) m[i] = g_mom[i * BMAX + b];   // coalesced
    const float* SW   = m;
    const float* SWs  = m + 6;
    const float* SWss = m + 24;
    const float* SWt  = m + 60;
    const float* SWts = m + 63;

    ull WP[5][6];
#pragma unroll
    for (int p = 0; p < 6; p++) {
        PK(WP[0][p], m[p],               m[6 + p * 3 + 0]);
        PK(WP[1][p], m[6 + p * 3 + 1],   m[6 + p * 3 + 2]);
        PK(WP[2][p], m[24 + p * 6 + 0],  m[24 + p * 6 + 1]);
        PK(WP[3][p], m[24 + p * 6 + 2],  m[24 + p * 6 + 3]);
        PK(WP[4][p], m[24 + p * 6 + 4],  m[24 + p * 6 + 5]);
    }

    const float* Ti = Tinit + b * 16;
    float R[9], t[3];
    R[0] = Ti[0];  R[1] = Ti[1];  R[2] = Ti[2];  t[0] = Ti[3];
    R[3] = Ti[4];  R[4] = Ti[5];  R[5] = Ti[6];  t[1] = Ti[7];
    R[6] = Ti[8];  R[7] = Ti[9];  R[8] = Ti[10]; t[2] = Ti[11];

    const int IDX[3][3] = {{0, 1, 2}, {1, 3, 4}, {2, 4, 5}};

#pragma unroll
    for (int it = 0; it < 10; ++it) {
        ull Rp[9];
#pragma unroll
        for (int i = 0; i < 9; i++) PK(Rp[i], R[i], R[i]);

        float A6[6], G[3][6], E[6][6];
        congr2(Rp, WP[0], A6,   G[0]);
        congr2(Rp, WP[1], G[1], G[2]);
        congr2(Rp, WP[2], E[0], E[1]);
        congr2(Rp, WP[3], E[2], E[3]);
        congr2(Rp, WP[4], E[4], E[5]);

        // --- assemble H (6x6 symmetric) ---
        float H[36];
#pragma unroll
        for (int p = 0; p < 3; p++)
#pragma unroll
            for (int q = 0; q < 3; q++) H[p * 6 + q] = A6[IDX[p][q]];
#pragma unroll
        for (int p = 0; p < 3; p++) {
            float h0 = G[1][IDX[p][2]] - G[2][IDX[p][1]];
            float h1 = G[2][IDX[p][0]] - G[0][IDX[p][2]];
            float h2 = G[0][IDX[p][1]] - G[1][IDX[p][0]];
            H[p * 6 + 3] = h0; H[p * 6 + 4] = h1; H[p * 6 + 5] = h2;
            H[3 * 6 + p] = h0; H[4 * 6 + p] = h1; H[5 * 6 + p] = h2;
        }
        {
            const int jp[3]  = {2, 0, 1}, mp[3]  = {1, 2, 0};
            const int jm[3]  = {1, 2, 0}, mmn[3] = {2, 0, 1};
#pragma unroll
            for (int k = 0; k < 3; k++)
#pragma unroll
                for (int l = 0; l < 3; l++) {
                    float h = E[IDX[mp[k]][mp[l]]][IDX[jp[k]][jp[l]]]
                            - E[IDX[mp[k]][mmn[l]]][IDX[jp[k]][jm[l]]]
                            - E[IDX[mmn[k]][mp[l]]][IDX[jm[k]][jp[l]]]
                            + E[IDX[mmn[k]][mmn[l]]][IDX[jm[k]][jm[l]]];
                    H[(3 + k) * 6 + (3 + l)] = h;
                }
        }
#pragma unroll
        for (int d = 0; d < 6; d++) H[d * 6 + d] += 1e-8f;

        // --- g ---
        float v[3];
#pragma unroll
        for (int a = 0; a < 3; a++) {
            float acc2 = SWt[a];
#pragma unroll
            for (int bb = 0; bb < 3; bb++) {
#pragma unroll
                for (int cc = 0; cc < 3; cc++)
                    acc2 -= R[bb * 3 + cc] * SWs[IDX[a][bb] * 3 + cc];
                acc2 -= SW[IDX[a][bb]] * t[bb];
            }
            v[a] = acc2;
        }
        float Ve[9];
#pragma unroll
        for (int a = 0; a < 3; a++)
#pragma unroll
            for (int mi = 0; mi < 3; mi++) {
                float acc2 = SWts[a * 3 + mi];
#pragma unroll
                for (int bb = 0; bb < 3; bb++) {
#pragma unroll
                    for (int cc = 0; cc < 3; cc++)
                        acc2 -= R[bb * 3 + cc] * SWss[IDX[a][bb] * 6 + IDX[cc][mi]];
                    acc2 -= t[bb] * SWs[IDX[a][bb] * 3 + mi];
                }
                Ve[a * 3 + mi] = acc2;
            }
        float g[6];
#pragma unroll
        for (int p = 0; p < 3; p++)
            g[p] = -(R[p] * v[0] + R[3 + p] * v[1] + R[6 + p] * v[2]);
        float F[9];
#pragma unroll
        for (int j = 0; j < 3; j++)
#pragma unroll
            for (int mi = 0; mi < 3; mi++)
                F[j * 3 + mi] = R[j] * Ve[mi] + R[3 + j] * Ve[3 + mi] + R[6 + j] * Ve[6 + mi];
        g[3] = F[1 * 3 + 2] - F[2 * 3 + 1];
        g[4] = F[2 * 3 + 0] - F[0 * 3 + 2];
        g[5] = F[0 * 3 + 1] - F[1 * 3 + 0];

        // --- block-Schur solve of H dx = -g ---
        // H = [A B; B^T C] (3x3 blocks), r = -g
        float Ai[6];
        inv3sym(H[0], H[1], H[2], H[7], H[8], H[14], Ai);
        // B[r][c] = H[r*6+3+c]
        float Bm[9] = {H[3], H[4], H[5], H[9], H[10], H[11], H[15], H[16], H[17]};
        // X = Ai * B
        float X[9];
#pragma unroll
        for (int j = 0; j < 3; j++) {
            X[0 * 3 + j] = Ai[0] * Bm[j] + Ai[1] * Bm[3 + j] + Ai[2] * Bm[6 + j];
            X[1 * 3 + j] = Ai[1] * Bm[j] + Ai[3] * Bm[3 + j] + Ai[4] * Bm[6 + j];
            X[2 * 3 + j] = Ai[2] * Bm[j] + Ai[4] * Bm[3 + j] + Ai[5] * Bm[6 + j];
        }
        // S = C - B^T X (symmetric; compute upper 6)
        float S00 = H[21] - (Bm[0] * X[0] + Bm[3] * X[3] + Bm[6] * X[6]);
        float S01 = H[22] - (Bm[0] * X[1] + Bm[3] * X[4] + Bm[6] * X[7]);
        float S02 = H[23] - (Bm[0] * X[2] + Bm[3] * X[5] + Bm[6] * X[8]);
        float S11 = H[28] - (Bm[1] * X[1] + Bm[4] * X[4] + Bm[7] * X[7]);
        float S12 = H[29] - (Bm[1] * X[2] + Bm[4] * X[5] + Bm[7] * X[8]);
        float S22 = H[35] - (Bm[2] * X[2] + Bm[5] * X[5] + Bm[8] * X[8]);
        float Si[6];
        inv3sym(S00, S01, S02, S11, S12, S22, Si);

        float r0a = -g[0], r1a = -g[1], r2a = -g[2];
        float r3a = -g[3], r4a = -g[4], r5a = -g[5];
        // u = Ai r0
        float u0 = Ai[0] * r0a + Ai[1] * r1a + Ai[2] * r2a;
        float u1 = Ai[1] * r0a + Ai[3] * r1a + Ai[4] * r2a;
        float u2 = Ai[2] * r0a + Ai[4] * r1a + Ai[5] * r2a;
        // t1 = r1 - B^T u
        float t1x = r3a - (Bm[0] * u0 + Bm[3] * u1 + Bm[6] * u2);
        float t1y = r4a - (Bm[1] * u0 + Bm[4] * u1 + Bm[7] * u2);
        float t1z = r5a - (Bm[2] * u0 + Bm[5] * u1 + Bm[8] * u2);
        // dx1 = Si t1
        float dx[6];
        dx[3] = Si[0] * t1x + Si[1] * t1y + Si[2] * t1z;
        dx[4] = Si[1] * t1x + Si[3] * t1y + Si[4] * t1z;
        dx[5] = Si[2] * t1x + Si[4] * t1y + Si[5] * t1z;
        // dx0 = u - X dx1
        dx[0] = u0 - (X[0] * dx[3] + X[1] * dx[4] + X[2] * dx[5]);
        dx[1] = u1 - (X[3] * dx[3] + X[4] * dx[4] + X[5] * dx[5]);
        dx[2] = u2 - (X[6] * dx[3] + X[7] * dx[4] + X[8] * dx[5]);

        // --- T <- T @ se3_exp(dx) ---
        float Re[9], te[3];
        se3exp(dx, Re, te);
        float Rn[9], tn[3];
#pragma unroll
        for (int r = 0; r < 3; r++) {
#pragma unroll
            for (int c = 0; c < 3; c++)
                Rn[r * 3 + c] = R[r * 3] * Re[c] + R[r * 3 + 1] * Re[3 + c] + R[r * 3 + 2] * Re[6 + c];
            tn[r] = R[r * 3] * te[0] + R[r * 3 + 1] * te[1] + R[r * 3 + 2] * te[2] + t[r];
        }
#pragma unroll
        for (int i = 0; i < 9; i++) R[i] = Rn[i];
#pragma unroll
        for (int i = 0; i < 3; i++) t[i] = tn[i];

        // warp-uniform early exit (skipped correction ~O(|dx|^2) ~ 1e-6)
        float mx = 0.f;
#pragma unroll
        for (int i = 0; i < 6; i++) mx = fmaxf(mx, fabsf(dx[i]));
        if (__all_sync(0xffffffffu, mx < 1e-3f)) break;
    }

    // --- out = inv(Tsv) @ T @ Tsv ---
    float Rs[9] = {Tsv[0], Tsv[1], Tsv[2], Tsv[4], Tsv[5], Tsv[6], Tsv[8], Tsv[9], Tsv[10]};
    float ts[3] = {Tsv[3], Tsv[7], Tsv[11]};
    float Rm[9], tm[3];
#pragma unroll
    for (int r = 0; r < 3; r++) {
#pragma unroll
        for (int c = 0; c < 3; c++)
            Rm[r * 3 + c] = R[r * 3] * Rs[c] + R[r * 3 + 1] * Rs[3 + c] + R[r * 3 + 2] * Rs[6 + c];
        tm[r] = R[r * 3] * ts[0] + R[r * 3 + 1] * ts[1] + R[r * 3 + 2] * ts[2] + t[r] - ts[r];
    }
    float* o = out + b * 16;
#pragma unroll
    for (int i = 0; i < 3; i++) {
#pragma unroll
        for (int j = 0; j < 3; j++)
            o[i * 4 + j] = Rs[i] * Rm[j] + Rs[3 + i] * Rm[3 + j] + Rs[6 + i] * Rm[6 + j];
        o[i * 4 + 3] = Rs[i] * tm[0] + Rs[3 + i] * tm[1] + Rs[6 + i] * tm[2];
    }
    o[12] = 0.f; o[13] = 0.f; o[14] = 0.f; o[15] = 1.f;
}

// ----------------------------------------------------------------------------
// Launch: fork a second stream so moments and gn are PARALLEL graph nodes.
// ----------------------------------------------------------------------------
extern "C" void kernel_launch(void* const* d_in, const int* in_sizes, int n_in,
                              void* d_out, int out_size)
{
    const float* src4  = (const float*)d_in[0];  // (B,4,N)
    const float* trg4  = (const float*)d_in[1];  // (B,4,N)
    const float* wgt   = (const float*)d_in[2];  // (B,1,N)
    const float* Tinit = (const float*)d_in[3];  // (B,4,4)
    const float* invc  = (const float*)d_in[4];  // (B,N,3,3)
    const float* Tsv   = (const float*)d_in[5];  // (4,4)
    float* out = (float*)d_out;                  // (B,4,4)

    int B = in_sizes[3] / 16;
    int N = in_sizes[2] / B;

    static cudaStream_t s2 = nullptr;
    static cudaEvent_t evFork = nullptr, evJoin = nullptr;
    if (s2 == nullptr) {
        cudaStreamCreateWithFlags(&s2, cudaStreamNonBlocking);
        cudaEventCreateWithFlags(&evFork, cudaEventDisableTiming);
        cudaEventCreateWithFlags(&evJoin, cudaEventDisableTiming);
    }

    cudaEventRecord(evFork, 0);
    cudaStreamWaitEvent(s2, evFork, 0);

    moments_kernel<<<B, 256>>>(src4, trg4, wgt, invc, N);           // stream 0
    gn_kernel<<<(B + 255) / 256, 256, 0, s2>>>(Tinit, Tsv, out, B); // stream s2

    cudaEventRecord(evJoin, s2);
    cudaStreamWaitEvent(0, evJoin, 0);
}